// round 16
// baseline (speedup 1.0000x reference)
#include <cuda_runtime.h>
#include <cuda_fp16.h>
#include <cstdint>
#include <cstddef>

#define BATCH 2048
#define ATOMS 64
#define DIN   384
#define NSPEC 4

// ---------------- device globals (no allocs allowed) ----------------
__device__ __half g_W0H[NSPEC][384][128];   // [s][k][n] fp16 (natural layout, no transpose)
__device__ __half g_W1H[NSPEC][128][128];
__device__ __half g_W2H[NSPEC][128][64];
__device__ float g_scratch[ATOMS * BATCH];  // [a][b] coalesced

// ---------------- smem layout (bytes) ----------------
#define STRIDE_B  144               // x/act tiles: 72 fp16/row (64+8 pad)
#define STRIDE_WK 272               // weight k-major rows: 128 n fp16 + 16B pad
#define TSA  (64 * STRIDE_B)        // 9216: one 64-row x 64-col x/act tile
#define TSW  (64 * STRIDE_WK)       // 17408: weight chunk 64k x 128n
#define TSW2 (64 * STRIDE_B)        // 9216: W2 chunk 64k x 64n (stride 144)
#define SM_ACT  0                   // 2 act tiles
#define SM_WB   (2 * TSA)           // 18432: 2 ping-pong weight buffers (TSW each)
#define SM_MISC (SM_WB + 2 * TSW)   // 53248
#define OFF_B0  (SM_MISC + 0)
#define OFF_B1  (SM_MISC + 512)
#define OFF_B2  (SM_MISC + 1024)
#define OFF_W3  (SM_MISC + 1280)
#define OFF_P   0                   // Ps aliases act tile 0 (dead after L2 MMA)
#define SMEM_TOTAL (SM_MISC + 1536) // 54784 -> <= 57344 (7x8KB) -> 4 CTAs/SM

// ---------------- PTX helpers (sm_80-level, portable) ----------------
__device__ __forceinline__ uint32_t smem_u32(const void* p) {
    uint32_t a;
    asm("{ .reg .u64 t; cvta.to.shared.u64 t, %1; cvt.u32.u64 %0, t; }" : "=r"(a) : "l"(p));
    return a;
}
__device__ __forceinline__ void ldsm4(uint32_t (&r)[4], uint32_t addr) {
    asm volatile("ldmatrix.sync.aligned.m8n8.x4.shared.b16 {%0,%1,%2,%3}, [%4];"
                 : "=r"(r[0]), "=r"(r[1]), "=r"(r[2]), "=r"(r[3]) : "r"(addr));
}
// transposed load: B fragments directly from k-major [k][n] tiles
__device__ __forceinline__ void ldsm4t(uint32_t (&r)[4], uint32_t addr) {
    asm volatile("ldmatrix.sync.aligned.m8n8.x4.trans.shared.b16 {%0,%1,%2,%3}, [%4];"
                 : "=r"(r[0]), "=r"(r[1]), "=r"(r[2]), "=r"(r[3]) : "r"(addr));
}
__device__ __forceinline__ void mma_f16(float (&c)[4], const uint32_t (&a)[4],
                                        uint32_t b0, uint32_t b1) {
    asm volatile("mma.sync.aligned.m16n8k16.row.col.f32.f16.f16.f32 "
                 "{%0,%1,%2,%3}, {%4,%5,%6,%7}, {%8,%9}, {%0,%1,%2,%3};"
                 : "+f"(c[0]), "+f"(c[1]), "+f"(c[2]), "+f"(c[3])
                 : "r"(a[0]), "r"(a[1]), "r"(a[2]), "r"(a[3]), "r"(b0), "r"(b1));
}
__device__ __forceinline__ void cp16(uint32_t dst, const void* src) {
    asm volatile("cp.async.cg.shared.global [%0], [%1], 16;" :: "r"(dst), "l"(src) : "memory");
}
#define CP_COMMIT() asm volatile("cp.async.commit_group;" ::: "memory")
#define CP_WAIT0()  asm volatile("cp.async.wait_group 0;" ::: "memory")
#define CP_WAIT1()  asm volatile("cp.async.wait_group 1;" ::: "memory")
#define STS32(addr, v) \
    asm volatile("st.shared.b32 [%0], %1;" :: "r"(addr), "r"(v) : "memory")
#define STS64(addr, a, b) \
    asm volatile("st.shared.v2.b32 [%0], {%1, %2};" :: "r"(addr), "r"(a), "r"(b) : "memory")

__device__ __forceinline__ uint32_t pack_f16x2(float f0, float f1) {
    __half2 h = __floats2half2_rn(f0, f1);
    return *(uint32_t*)&h;
}

// ---------------- prep: pure streaming fp32 -> fp16 convert (no transpose) ----------------
__global__ void prep_kernel(const float* __restrict__ W0, const float* __restrict__ W1,
                            const float* __restrict__ W2)
{
    const int P0 = NSPEC * 384 * 128 / 2;   // 98304 pairs
    const int P1 = NSPEC * 128 * 128 / 2;   // 32768
    int p = blockIdx.x * blockDim.x + threadIdx.x;  // 0..147455
    const float2* src; __half2* dst; int off;
    if (p < P0)            { src = (const float2*)W0; dst = (__half2*)&g_W0H[0][0][0]; off = p; }
    else if (p < P0 + P1)  { src = (const float2*)W1; dst = (__half2*)&g_W1H[0][0][0]; off = p - P0; }
    else                   { src = (const float2*)W2; dst = (__half2*)&g_W2H[0][0][0]; off = p - P0 - P1; }
    float2 v = src[off];
    dst[off] = __floats2half2_rn(v.x, v.y);
}

// single-pass chunk: K=64 (4 k-steps), 2 m-frags, NF n-frags of 8; B via trans-ldsm
template<int NF, int WSTR>
__device__ __forceinline__ void chunk_mma(float (&acc)[2][4][4],
                                          uint32_t aBase, uint32_t bBase)
{
#pragma unroll
    for (int ks = 0; ks < 4; ++ks) {
        uint32_t bh[(NF + 1) / 2][4];
#pragma unroll
        for (int p = 0; p < (NF + 1) / 2; ++p)
            ldsm4t(bh[p], bBase + p * 32 + ks * (16 * WSTR));
#pragma unroll
        for (int mf = 0; mf < 2; ++mf) {
            uint32_t ah[4];
            ldsm4(ah, aBase + mf * (16 * STRIDE_B) + ks * 32);
#pragma unroll
            for (int np = 0; np < NF; ++np)
                mma_f16(acc[mf][np], ah,
                        bh[np >> 1][(np & 1) * 2], bh[np >> 1][(np & 1) * 2 + 1]);
        }
    }
}

// bias + exp(-y^2) -> fp16 act tiles (c0 -> tile0, c1 -> tile1); warp tile 32x32
__device__ __forceinline__ void epilogue_store(float (&acc)[2][4][4], const float* bias,
                                               uint32_t sb, int m0, int n0, int lane)
{
#pragma unroll
    for (int mf = 0; mf < 2; ++mf) {
#pragma unroll
        for (int np = 0; np < 4; ++np) {
            int n = n0 + np * 8 + 2 * (lane & 3);
            int c = n >> 6;
            int nn = n & 63;
            float bv0 = bias[n], bv1 = bias[n + 1];
            uint32_t tileT = sb + SM_ACT + c * TSA;
            int r0 = m0 + mf * 16 + (lane >> 2);
            float y0 = acc[mf][np][0] + bv0, y1 = acc[mf][np][1] + bv1;
            uint32_t addr = tileT + r0 * STRIDE_B + nn * 2;
            STS32(addr, pack_f16x2(__expf(-y0 * y0), __expf(-y1 * y1)));
            float y2 = acc[mf][np][2] + bv0, y3 = acc[mf][np][3] + bv1;
            STS32(addr + 8 * STRIDE_B, pack_f16x2(__expf(-y2 * y2), __expf(-y3 * y3)));
        }
    }
}

// ---------------- main fused MLP kernel (R14 structure, k-major weights) ----------------
__global__ void __launch_bounds__(256, 4)
mlp_mma_kernel(const float* __restrict__ x, const int* __restrict__ species,
               const float* __restrict__ b0, const float* __restrict__ b1,
               const float* __restrict__ b2, const float* __restrict__ W3,
               const float* __restrict__ b3)
{
    extern __shared__ char smem[];
    const uint32_t sb = smem_u32(smem);
    const int tid  = threadIdx.x;
    const int wid  = tid >> 5;
    const int lane = tid & 31;
    const int btile = blockIdx.x;       // 0..31 (64 batch rows)
    const int a     = blockIdx.y;       // 0..63
    const int s     = __ldg(species + a);

    float* b0s = (float*)(smem + OFF_B0);
    float* b1s = (float*)(smem + OFF_B1);
    float* b2s = (float*)(smem + OFF_B2);
    float* w3s = (float*)(smem + OFF_W3);
    float* Ps  = (float*)(smem + OFF_P);    // aliases act tile 0 (used post-L2 only)
    if (tid < 128) {
        b0s[tid] = __ldg(b0 + s * 128 + tid);
        b1s[tid] = __ldg(b1 + s * 128 + tid);
    }
    if (tid < 64) {
        b2s[tid] = __ldg(b2 + s * 64 + tid);
        w3s[tid] = __ldg(W3 + s * 64 + tid);
    }

    const float* xb = x + ((size_t)btile * 64 * ATOMS + a) * DIN;
    const __half* w0 = &g_W0H[s][0][0];     // [384][128] k-major
    const __half* w1 = &g_W1H[s][0][0];     // [128][128]
    const __half* w2 = &g_W2H[s][0][0];     // [128][64]

    // per-lane ldmatrix address components
    const int arow = (lane & 7) + ((lane >> 3) & 1) * 8;
    const int acol = (lane & 16) ? 16 : 0;
    const int bkrow = lane & 15;            // k-row within 16x16 tile (trans load)
    const int bncol = (lane >> 4) * 16;     // n-half byte offset
    const int m0   = (wid & 1) * 32;        // 2 m-warps (M=64)
    const int n0   = (wid >> 1) * 32;       // 4 n-warps (N=128)
    const int n0_2 = (wid >> 1) * 16;       // 4 n-warps (N=64)

    const uint32_t aBase   = sb + SM_ACT + (m0 + arow) * STRIDE_B + acol; // + tile*TSA
    const uint32_t bBaseN  = sb + SM_WB + bkrow * STRIDE_WK + bncol + n0 * 2;   // + buf*TSW
    const uint32_t bBaseN2 = sb + SM_WB + bkrow * STRIDE_B  + bncol + n0_2 * 2; // + buf*TSW2

    float acc[2][4][4];
#pragma unroll
    for (int i = 0; i < 2; ++i)
#pragma unroll
        for (int j = 0; j < 4; ++j)
#pragma unroll
            for (int q = 0; q < 4; ++q) acc[i][j][q] = 0.f;

    // prefetch W0 chunk 0 -> wbuf 0 (64 k-rows x 128 n, 16 units/row)
#pragma unroll
    for (int i = 0; i < 4; ++i) {
        int idx = tid + i * 256;              // 0..1023 16B units
        int row = idx >> 4, seg = idx & 15;
        cp16(sb + SM_WB + row * STRIDE_WK + seg * 16, w0 + row * 128 + seg * 8);
    }
    CP_COMMIT();

    // stage x chunk 0 -> tile 0 (fp32 -> fp16); 64 rows x 16 float4
#pragma unroll
    for (int i = 0; i < 4; ++i) {
        int idx = tid + i * 256;              // 0..1023 float4s
        int row = idx >> 4;
        int c4  = (idx & 15) * 4;
        float4 v = *(const float4*)(xb + (size_t)row * (ATOMS * DIN) + c4);
        STS64(sb + SM_ACT + row * STRIDE_B + c4 * 2,
              pack_f16x2(v.x, v.y), pack_f16x2(v.z, v.w));
    }
    CP_WAIT0();
    __syncthreads();

    // ================= Layer 0: K=384, 6 chunks, x+w double-buffered =================
    for (int kc = 0; kc < 6; ++kc) {
        if (kc < 5) {
            // prefetch next weight chunk (async) into other wbuf
#pragma unroll
            for (int i = 0; i < 4; ++i) {
                int idx = tid + i * 256;
                int row = idx >> 4, seg = idx & 15;
                uint32_t dst = sb + SM_WB + ((kc + 1) & 1) * TSW + row * STRIDE_WK + seg * 16;
                cp16(dst, w0 + ((kc + 1) * 64 + row) * 128 + seg * 8);
            }
            CP_COMMIT();
            // stage next x chunk into the tile current MMA is NOT reading
#pragma unroll
            for (int i = 0; i < 4; ++i) {
                int idx = tid + i * 256;
                int row = idx >> 4;
                int c4  = (idx & 15) * 4;
                float4 v = *(const float4*)(xb + (size_t)row * (ATOMS * DIN) + (kc + 1) * 64 + c4);
                STS64(sb + SM_ACT + ((kc + 1) & 1) * TSA + row * STRIDE_B + c4 * 2,
                      pack_f16x2(v.x, v.y), pack_f16x2(v.z, v.w));
            }
            CP_WAIT1();   // weight chunk kc complete; kc+1 still in flight
        }
        chunk_mma<4, STRIDE_WK>(acc, aBase + (kc & 1) * TSA, bBaseN + (kc & 1) * TSW);
        __syncthreads();
    }

    // prefetch W1 both chunks (wbuf0, wbuf1), overlap with epilogue 0
#pragma unroll
    for (int i = 0; i < 8; ++i) {
        int idx = tid + i * 256;              // 0..2047
        int c = idx >> 10;                    // chunk 0/1 -> wbuf 0/1
        int v = idx & 1023;
        int row = v >> 4, seg = v & 15;
        uint32_t dst = sb + SM_WB + c * TSW + row * STRIDE_WK + seg * 16;
        cp16(dst, w1 + (c * 64 + row) * 128 + seg * 8);
    }
    CP_COMMIT();

    // epilogue 0: acc -> act tiles 0/1 (x staging done, tiles dead)
    epilogue_store(acc, b0s, sb, m0, n0, lane);
    CP_WAIT0();
    __syncthreads();

    // ================= Layer 1: K=128, 2 chunks chained =================
#pragma unroll
    for (int i = 0; i < 2; ++i)
#pragma unroll
        for (int j = 0; j < 4; ++j)
#pragma unroll
            for (int q = 0; q < 4; ++q) acc[i][j][q] = 0.f;

    chunk_mma<4, STRIDE_WK>(acc, aBase, bBaseN);
    chunk_mma<4, STRIDE_WK>(acc, aBase + TSA, bBaseN + TSW);
    __syncthreads();

    // prefetch W2 both chunks (64 k-rows x 64 n each, stride 144)
#pragma unroll
    for (int i = 0; i < 4; ++i) {
        int idx = tid + i * 256;              // 0..1023 16B units
        int c = idx >> 9;                     // chunk 0/1
        int v = idx & 511;
        int row = v >> 3, seg = v & 7;
        uint32_t dst = sb + SM_WB + c * TSW2 + row * STRIDE_B + seg * 16;
        cp16(dst, w2 + (c * 64 + row) * 64 + seg * 8);
    }
    CP_COMMIT();

    epilogue_store(acc, b1s, sb, m0, n0, lane);
    CP_WAIT0();
    __syncthreads();

    // ================= Layer 2: K=128, N=64 (warp tile 32x16) =================
#pragma unroll
    for (int i = 0; i < 2; ++i)
#pragma unroll
        for (int j = 0; j < 4; ++j)
#pragma unroll
            for (int q = 0; q < 4; ++q) acc[i][j][q] = 0.f;

    chunk_mma<2, STRIDE_B>(acc, aBase, bBaseN2);
    chunk_mma<2, STRIDE_B>(acc, aBase + TSA, bBaseN2 + TSW2);
    __syncthreads();   // all warps done reading act tiles before Ps (aliased) is written

    // ================= epilogue 2 + layer 3 dot + partials =================
    {
        const int ng = wid >> 1;    // n-group 0..3
#pragma unroll
        for (int mf = 0; mf < 2; ++mf) {
            float s0 = 0.f, s1 = 0.f;
#pragma unroll
            for (int np = 0; np < 2; ++np) {
                int n = n0_2 + np * 8 + 2 * (lane & 3);
                float bv0 = b2s[n], bv1 = b2s[n + 1];
                float wv0 = w3s[n], wv1 = w3s[n + 1];
                float y0 = acc[mf][np][0] + bv0, y1 = acc[mf][np][1] + bv1;
                s0 = fmaf(__expf(-y0 * y0), wv0, s0);
                s0 = fmaf(__expf(-y1 * y1), wv1, s0);
                float y2 = acc[mf][np][2] + bv0, y3 = acc[mf][np][3] + bv1;
                s1 = fmaf(__expf(-y2 * y2), wv0, s1);
                s1 = fmaf(__expf(-y3 * y3), wv1, s1);
            }
            s0 += __shfl_xor_sync(0xFFFFFFFFu, s0, 1);
            s0 += __shfl_xor_sync(0xFFFFFFFFu, s0, 2);
            s1 += __shfl_xor_sync(0xFFFFFFFFu, s1, 1);
            s1 += __shfl_xor_sync(0xFFFFFFFFu, s1, 2);
            if ((lane & 3) == 0) {
                int r = m0 + mf * 16 + (lane >> 2);
                Ps[ng * 64 + r]     = s0;
                Ps[ng * 64 + r + 8] = s1;
            }
        }
    }
    __syncthreads();
    if (tid < 64) {
        float v = Ps[tid] + Ps[64 + tid] + Ps[128 + tid] + Ps[192 + tid] + __ldg(b3 + s);
        g_scratch[(size_t)a * BATCH + btile * 64 + tid] = v;   // coalesced
    }
}

// ---------------- deterministic atom reduction (coalesced, MLP=8) ----------------
__global__ void reduce_kernel(float* __restrict__ out)
{
    int b = blockIdx.x * blockDim.x + threadIdx.x;   // 2048 threads
    float s0 = 0.f, s1 = 0.f, s2 = 0.f, s3 = 0.f;
    float s4 = 0.f, s5 = 0.f, s6 = 0.f, s7 = 0.f;
#pragma unroll
    for (int a8 = 0; a8 < ATOMS; a8 += 8) {
        s0 += g_scratch[(size_t)(a8 + 0) * BATCH + b];
        s1 += g_scratch[(size_t)(a8 + 1) * BATCH + b];
        s2 += g_scratch[(size_t)(a8 + 2) * BATCH + b];
        s3 += g_scratch[(size_t)(a8 + 3) * BATCH + b];
        s4 += g_scratch[(size_t)(a8 + 4) * BATCH + b];
        s5 += g_scratch[(size_t)(a8 + 5) * BATCH + b];
        s6 += g_scratch[(size_t)(a8 + 6) * BATCH + b];
        s7 += g_scratch[(size_t)(a8 + 7) * BATCH + b];
    }
    out[b] = ((s0 + s1) + (s2 + s3)) + ((s4 + s5) + (s6 + s7));
}

extern "C" void kernel_launch(void* const* d_in, const int* in_sizes, int n_in,
                              void* d_out, int out_size)
{
    const float* x       = (const float*)d_in[0];
    const int*   species = (const int*)  d_in[1];
    const float* W0      = (const float*)d_in[2];
    const float* b0      = (const float*)d_in[3];
    const float* W1      = (const float*)d_in[4];
    const float* b1      = (const float*)d_in[5];
    const float* W2      = (const float*)d_in[6];
    const float* b2      = (const float*)d_in[7];
    const float* W3      = (const float*)d_in[8];
    const float* b3      = (const float*)d_in[9];
    float*       out     = (float*)d_out;

    cudaFuncSetAttribute(mlp_mma_kernel,
                         cudaFuncAttributeMaxDynamicSharedMemorySize, SMEM_TOTAL);

    // 147456 pairs / 256 = 576 CTAs, one half2 per thread (pure streaming convert)
    prep_kernel<<<576, 256>>>(W0, W1, W2);

    dim3 grid(BATCH / 64, ATOMS);
    mlp_mma_kernel<<<grid, 256, SMEM_TOTAL>>>(x, species, b0, b1, b2, W3, b3);

    reduce_kernel<<<8, 256>>>(out);
}

// round 17
// speedup vs baseline: 1.0226x; 1.0226x over previous
#include <cuda_runtime.h>
#include <cuda_fp16.h>
#include <cstdint>
#include <cstddef>

#define BATCH 2048
#define ATOMS 64
#define DIN   384
#define NSPEC 4

// ---------------- device globals (no allocs allowed) ----------------
__device__ __half g_W0H[NSPEC][128][384];   // [s][n][k] fp16
__device__ __half g_W1H[NSPEC][128][128];
__device__ __half g_W2H[NSPEC][64][128];
__device__ float g_scratch[ATOMS * BATCH];  // [a][b] coalesced
__device__ int   g_cnt[BATCH / 64];         // per-btile arrival counters (zeroed by prep)

// ---------------- smem layout (bytes) ----------------
#define STRIDE_B 144                 // 72 fp16 per row (64 + 8 pad) -> conflict-free ldsm
#define TSA (64 * STRIDE_B)          // 9216: one 64-row x 64-col fp16 act/x tile
#define TSW (128 * STRIDE_B)         // 18432: one 128-row weight tile
#define SM_ACT  0                    // 2 act tiles (x ping-pong in L0, act c0/c1 after)
#define SM_WB   (2 * TSA)            // 2 ping-pong weight buffers
#define SM_MISC (2 * TSA + 2 * TSW)  // 55296
#define OFF_B0  (SM_MISC + 0)
#define OFF_B1  (SM_MISC + 512)
#define OFF_B2  (SM_MISC + 1024)
#define OFF_W3  (SM_MISC + 1280)
#define OFF_P   0                    // Ps aliases act tile 0 (dead after L2 MMA)
#define SMEM_TOTAL (SM_MISC + 1536)  // 56832 -> rounds to 57344 (7x8KB) -> 4 CTAs/SM

// ---------------- PTX helpers (sm_80-level, portable) ----------------
__device__ __forceinline__ uint32_t smem_u32(const void* p) {
    uint32_t a;
    asm("{ .reg .u64 t; cvta.to.shared.u64 t, %1; cvt.u32.u64 %0, t; }" : "=r"(a) : "l"(p));
    return a;
}
__device__ __forceinline__ void ldsm4(uint32_t (&r)[4], uint32_t addr) {
    asm volatile("ldmatrix.sync.aligned.m8n8.x4.shared.b16 {%0,%1,%2,%3}, [%4];"
                 : "=r"(r[0]), "=r"(r[1]), "=r"(r[2]), "=r"(r[3]) : "r"(addr));
}
__device__ __forceinline__ void mma_f16(float (&c)[4], const uint32_t (&a)[4],
                                        uint32_t b0, uint32_t b1) {
    asm volatile("mma.sync.aligned.m16n8k16.row.col.f32.f16.f16.f32 "
                 "{%0,%1,%2,%3}, {%4,%5,%6,%7}, {%8,%9}, {%0,%1,%2,%3};"
                 : "+f"(c[0]), "+f"(c[1]), "+f"(c[2]), "+f"(c[3])
                 : "r"(a[0]), "r"(a[1]), "r"(a[2]), "r"(a[3]), "r"(b0), "r"(b1));
}
__device__ __forceinline__ void cp16(uint32_t dst, const void* src) {
    asm volatile("cp.async.cg.shared.global [%0], [%1], 16;" :: "r"(dst), "l"(src) : "memory");
}
#define CP_COMMIT() asm volatile("cp.async.commit_group;" ::: "memory")
#define CP_WAIT0()  asm volatile("cp.async.wait_group 0;" ::: "memory")
#define CP_WAIT1()  asm volatile("cp.async.wait_group 1;" ::: "memory")
#define STS32(addr, v) \
    asm volatile("st.shared.b32 [%0], %1;" :: "r"(addr), "r"(v) : "memory")
#define STS64(addr, a, b) \
    asm volatile("st.shared.v2.b32 [%0], {%1, %2};" :: "r"(addr), "r"(a), "r"(b) : "memory")

__device__ __forceinline__ uint32_t pack_f16x2(float f0, float f1) {
    __half2 h = __floats2half2_rn(f0, f1);
    return *(uint32_t*)&h;
}

// ---------------- prep: 64k x 32n tile transpose, half2 writes (R14) + counter reset ----------------
__global__ void prep_kernel(const float* __restrict__ W0, const float* __restrict__ W1,
                            const float* __restrict__ W2)
{
    __shared__ float t[64][33];
    const int tile = blockIdx.x;
    const int tid  = threadIdx.x;
    if (tile == 0 && tid < BATCH / 64) g_cnt[tid] = 0;   // reset arrival counters
    const float* src; __half* dst; int K, N, kt, nt;
    if (tile < 96) {
        int s = tile / 24, r = tile % 24; kt = r >> 2; nt = r & 3;
        src = W0 + (size_t)s * 384 * 128; dst = &g_W0H[s][0][0]; K = 384; N = 128;
    } else if (tile < 128) {
        int t2 = tile - 96; int s = t2 / 8, r = t2 % 8; kt = r >> 2; nt = r & 3;
        src = W1 + (size_t)s * 128 * 128; dst = &g_W1H[s][0][0]; K = 128; N = 128;
    } else {
        int t3 = tile - 128; int s = t3 / 4, r = t3 % 4; kt = r >> 1; nt = r & 1;
        src = W2 + (size_t)s * 128 * 64; dst = &g_W2H[s][0][0]; K = 128; N = 64;
    }
    const int k0 = kt * 64, n0 = nt * 32;
#pragma unroll
    for (int i = 0; i < 8; ++i) {
        int idx = tid + i * 256;
        int kr = idx >> 5, nc = idx & 31;
        t[kr][nc] = src[(size_t)(k0 + kr) * N + n0 + nc];
    }
    __syncthreads();
#pragma unroll
    for (int i = 0; i < 4; ++i) {
        int idx = tid + i * 256;
        int nr = idx >> 5, kc = idx & 31;
        __half2 v = __floats2half2_rn(t[2 * kc][nr], t[2 * kc + 1][nr]);
        *(__half2*)(dst + (size_t)(n0 + nr) * K + k0 + 2 * kc) = v;
    }
}

// single-pass chunk: K=64 (4 k-steps), 2 m-frags (32 rows), NF n-frags of 8
template<int NF>
__device__ __forceinline__ void chunk_mma(float (&acc)[2][4][4],
                                          uint32_t aBase, uint32_t bBase)
{
#pragma unroll
    for (int ks = 0; ks < 4; ++ks) {
        uint32_t bh[(NF + 1) / 2][4];
#pragma unroll
        for (int p = 0; p < (NF + 1) / 2; ++p)
            ldsm4(bh[p], bBase + p * (16 * STRIDE_B) + ks * 32);
#pragma unroll
        for (int mf = 0; mf < 2; ++mf) {
            uint32_t ah[4];
            ldsm4(ah, aBase + mf * (16 * STRIDE_B) + ks * 32);
#pragma unroll
            for (int np = 0; np < NF; ++np)
                mma_f16(acc[mf][np], ah,
                        bh[np >> 1][(np & 1) * 2], bh[np >> 1][(np & 1) * 2 + 1]);
        }
    }
}

// bias + exp(-y^2) -> fp16 act tiles (c0 -> tile0, c1 -> tile1); warp tile 32x32
__device__ __forceinline__ void epilogue_store(float (&acc)[2][4][4], const float* bias,
                                               uint32_t sb, int m0, int n0, int lane)
{
#pragma unroll
    for (int mf = 0; mf < 2; ++mf) {
#pragma unroll
        for (int np = 0; np < 4; ++np) {
            int n = n0 + np * 8 + 2 * (lane & 3);
            int c = n >> 6;
            int nn = n & 63;
            float bv0 = bias[n], bv1 = bias[n + 1];
            uint32_t tileT = sb + SM_ACT + c * TSA;
            int r0 = m0 + mf * 16 + (lane >> 2);
            float y0 = acc[mf][np][0] + bv0, y1 = acc[mf][np][1] + bv1;
            uint32_t addr = tileT + r0 * STRIDE_B + nn * 2;
            STS32(addr, pack_f16x2(__expf(-y0 * y0), __expf(-y1 * y1)));
            float y2 = acc[mf][np][2] + bv0, y3 = acc[mf][np][3] + bv1;
            STS32(addr + 8 * STRIDE_B, pack_f16x2(__expf(-y2 * y2), __expf(-y3 * y3)));
        }
    }
}

// ---------------- main fused MLP kernel (R14 main + fused last-CTA reduction) ----------------
__global__ void __launch_bounds__(256, 4)
mlp_mma_kernel(const float* __restrict__ x, const int* __restrict__ species,
               const float* __restrict__ b0, const float* __restrict__ b1,
               const float* __restrict__ b2, const float* __restrict__ W3,
               const float* __restrict__ b3, float* __restrict__ out)
{
    extern __shared__ char smem[];
    __shared__ int isLast;
    const uint32_t sb = smem_u32(smem);
    const int tid  = threadIdx.x;
    const int wid  = tid >> 5;
    const int lane = tid & 31;
    const int btile = blockIdx.x;       // 0..31 (64 batch rows)
    const int a     = blockIdx.y;       // 0..63
    const int s     = __ldg(species + a);

    float* b0s = (float*)(smem + OFF_B0);
    float* b1s = (float*)(smem + OFF_B1);
    float* b2s = (float*)(smem + OFF_B2);
    float* w3s = (float*)(smem + OFF_W3);
    float* Ps  = (float*)(smem + OFF_P);    // aliases act tile 0 (used post-L2 only)
    if (tid < 128) {
        b0s[tid] = __ldg(b0 + s * 128 + tid);
        b1s[tid] = __ldg(b1 + s * 128 + tid);
    }
    if (tid < 64) {
        b2s[tid] = __ldg(b2 + s * 64 + tid);
        w3s[tid] = __ldg(W3 + s * 64 + tid);
    }

    const float* xb = x + ((size_t)btile * 64 * ATOMS + a) * DIN;
    const __half* w0 = &g_W0H[s][0][0];
    const __half* w1 = &g_W1H[s][0][0];
    const __half* w2 = &g_W2H[s][0][0];

    // per-lane ldmatrix address components
    const int arow = (lane & 7) + ((lane >> 3) & 1) * 8;
    const int acol = (lane & 16) ? 16 : 0;
    const int brow = (lane & 7) + ((lane >> 4) & 1) * 8;
    const int bcol = (lane & 8) ? 16 : 0;
    const int m0   = (wid & 1) * 32;     // 2 m-warps (M=64)
    const int n0   = (wid >> 1) * 32;    // 4 n-warps (N=128)
    const int n0_2 = (wid >> 1) * 16;    // 4 n-warps (N=64)

    const uint32_t aBase   = sb + SM_ACT + (m0 + arow) * STRIDE_B + acol; // + tile*TSA
    const uint32_t bWRow   = sb + SM_WB + brow * STRIDE_B + bcol;         // + buf*TSW
    const uint32_t bBaseN  = bWRow + n0 * STRIDE_B;
    const uint32_t bBaseN2 = bWRow + n0_2 * STRIDE_B;

    float acc[2][4][4];
#pragma unroll
    for (int i = 0; i < 2; ++i)
#pragma unroll
        for (int j = 0; j < 4; ++j)
#pragma unroll
            for (int q = 0; q < 4; ++q) acc[i][j][q] = 0.f;

    // prefetch W0 chunk 0 -> wbuf 0 (cp.async)
#pragma unroll
    for (int i = 0; i < 4; ++i) {
        int idx = tid + i * 256;              // 0..1023 16B units
        int row = idx >> 3, seg = idx & 7;
        cp16(sb + SM_WB + row * STRIDE_B + seg * 16, w0 + row * 384 + seg * 8);
    }
    CP_COMMIT();

    // stage x chunk 0 -> tile 0 (fp32 -> fp16); 64 rows x 16 float4
#pragma unroll
    for (int i = 0; i < 4; ++i) {
        int idx = tid + i * 256;              // 0..1023 float4s
        int row = idx >> 4;
        int c4  = (idx & 15) * 4;
        float4 v = *(const float4*)(xb + (size_t)row * (ATOMS * DIN) + c4);
        STS64(sb + SM_ACT + row * STRIDE_B + c4 * 2,
              pack_f16x2(v.x, v.y), pack_f16x2(v.z, v.w));
    }
    CP_WAIT0();
    __syncthreads();

    // ================= Layer 0: K=384, 6 chunks, x+w double-buffered =================
    for (int kc = 0; kc < 6; ++kc) {
        if (kc < 5) {
            // prefetch next weight chunk (async) into other wbuf
#pragma unroll
            for (int i = 0; i < 4; ++i) {
                int idx = tid + i * 256;
                int row = idx >> 3, seg = idx & 7;
                uint32_t dst = sb + SM_WB + ((kc + 1) & 1) * TSW + row * STRIDE_B + seg * 16;
                cp16(dst, w0 + row * 384 + (kc + 1) * 64 + seg * 8);
            }
            CP_COMMIT();
            // stage next x chunk into the tile current MMA is NOT reading
#pragma unroll
            for (int i = 0; i < 4; ++i) {
                int idx = tid + i * 256;
                int row = idx >> 4;
                int c4  = (idx & 15) * 4;
                float4 v = *(const float4*)(xb + (size_t)row * (ATOMS * DIN) + (kc + 1) * 64 + c4);
                STS64(sb + SM_ACT + ((kc + 1) & 1) * TSA + row * STRIDE_B + c4 * 2,
                      pack_f16x2(v.x, v.y), pack_f16x2(v.z, v.w));
            }
            CP_WAIT1();   // weight chunk kc complete; kc+1 still in flight
        }
        chunk_mma<4>(acc, aBase + (kc & 1) * TSA, bBaseN + (kc & 1) * TSW);
        __syncthreads();
    }

    // prefetch W1 both chunks (wbuf0, wbuf1), overlap with epilogue 0
#pragma unroll
    for (int i = 0; i < 8; ++i) {
        int idx = tid + i * 256;              // 0..2047
        int c = idx >> 10;                    // chunk 0/1 -> wbuf 0/1
        int v = idx & 1023;
        int row = v >> 3, seg = v & 7;
        uint32_t dst = sb + SM_WB + c * TSW + row * STRIDE_B + seg * 16;
        cp16(dst, w1 + row * 128 + c * 64 + seg * 8);
    }
    CP_COMMIT();

    // epilogue 0: acc -> act tiles 0/1 (x staging done, tiles dead)
    epilogue_store(acc, b0s, sb, m0, n0, lane);
    CP_WAIT0();
    __syncthreads();

    // ================= Layer 1: K=128, 2 chunks chained =================
#pragma unroll
    for (int i = 0; i < 2; ++i)
#pragma unroll
        for (int j = 0; j < 4; ++j)
#pragma unroll
            for (int q = 0; q < 4; ++q) acc[i][j][q] = 0.f;

    chunk_mma<4>(acc, aBase, bBaseN);
    chunk_mma<4>(acc, aBase + TSA, bBaseN + TSW);
    __syncthreads();

    // prefetch W2 both chunks (64 n-rows each), overlap with epilogue 1
#pragma unroll
    for (int i = 0; i < 4; ++i) {
        int idx = tid + i * 256;              // 0..1023
        int c = idx >> 9;
        int v = idx & 511;
        int row = v >> 3, seg = v & 7;
        uint32_t dst = sb + SM_WB + c * TSW + row * STRIDE_B + seg * 16;
        cp16(dst, w2 + row * 128 + c * 64 + seg * 8);
    }
    CP_COMMIT();

    epilogue_store(acc, b1s, sb, m0, n0, lane);
    CP_WAIT0();
    __syncthreads();

    // ================= Layer 2: K=128, N=64 (warp tile 32x16) =================
#pragma unroll
    for (int i = 0; i < 2; ++i)
#pragma unroll
        for (int j = 0; j < 4; ++j)
#pragma unroll
            for (int q = 0; q < 4; ++q) acc[i][j][q] = 0.f;

    chunk_mma<2>(acc, aBase, bBaseN2);
    chunk_mma<2>(acc, aBase + TSA, bBaseN2 + TSW);
    __syncthreads();   // all warps done reading act tiles before Ps (aliased) is written

    // ================= epilogue 2 + layer 3 dot + partials =================
    {
        const int ng = wid >> 1;    // n-group 0..3
#pragma unroll
        for (int mf = 0; mf < 2; ++mf) {
            float s0 = 0.f, s1 = 0.f;
#pragma unroll
            for (int np = 0; np < 2; ++np) {
                int n = n0_2 + np * 8 + 2 * (lane & 3);
                float bv0 = b2s[n], bv1 = b2s[n + 1];
                float wv0 = w3s[n], wv1 = w3s[n + 1];
                float y0 = acc[mf][np][0] + bv0, y1 = acc[mf][np][1] + bv1;
                s0 = fmaf(__expf(-y0 * y0), wv0, s0);
                s0 = fmaf(__expf(-y1 * y1), wv1, s0);
                float y2 = acc[mf][np][2] + bv0, y3 = acc[mf][np][3] + bv1;
                s1 = fmaf(__expf(-y2 * y2), wv0, s1);
                s1 = fmaf(__expf(-y3 * y3), wv1, s1);
            }
            s0 += __shfl_xor_sync(0xFFFFFFFFu, s0, 1);
            s0 += __shfl_xor_sync(0xFFFFFFFFu, s0, 2);
            s1 += __shfl_xor_sync(0xFFFFFFFFu, s1, 1);
            s1 += __shfl_xor_sync(0xFFFFFFFFu, s1, 2);
            if ((lane & 3) == 0) {
                int r = m0 + mf * 16 + (lane >> 2);
                Ps[ng * 64 + r]     = s0;
                Ps[ng * 64 + r + 8] = s1;
            }
        }
    }
    __syncthreads();
    if (tid < 64) {
        float v = Ps[tid] + Ps[64 + tid] + Ps[128 + tid] + Ps[192 + tid] + __ldg(b3 + s);
        g_scratch[(size_t)a * BATCH + btile * 64 + tid] = v;   // coalesced
    }

    // ================= fused deterministic reduction (last CTA per btile) =================
    __threadfence();                       // publish g_scratch row
    if (tid == 0)
        isLast = (atomicAdd(&g_cnt[btile], 1) == ATOMS - 1);
    __syncthreads();
    if (isLast) {
        __threadfence();                   // acquire all producers' g_scratch rows
        if (tid < 64) {
            int b = btile * 64 + tid;
            float s0 = 0.f, s1 = 0.f, s2 = 0.f, s3 = 0.f;
            float s4 = 0.f, s5 = 0.f, s6 = 0.f, s7 = 0.f;
#pragma unroll
            for (int a8 = 0; a8 < ATOMS; a8 += 8) {
                s0 += g_scratch[(size_t)(a8 + 0) * BATCH + b];
                s1 += g_scratch[(size_t)(a8 + 1) * BATCH + b];
                s2 += g_scratch[(size_t)(a8 + 2) * BATCH + b];
                s3 += g_scratch[(size_t)(a8 + 3) * BATCH + b];
                s4 += g_scratch[(size_t)(a8 + 4) * BATCH + b];
                s5 += g_scratch[(size_t)(a8 + 5) * BATCH + b];
                s6 += g_scratch[(size_t)(a8 + 6) * BATCH + b];
                s7 += g_scratch[(size_t)(a8 + 7) * BATCH + b];
            }
            out[b] = ((s0 + s1) + (s2 + s3)) + ((s4 + s5) + (s6 + s7));
        }
    }
}

extern "C" void kernel_launch(void* const* d_in, const int* in_sizes, int n_in,
                              void* d_out, int out_size)
{
    const float* x       = (const float*)d_in[0];
    const int*   species = (const int*)  d_in[1];
    const float* W0      = (const float*)d_in[2];
    const float* b0      = (const float*)d_in[3];
    const float* W1      = (const float*)d_in[4];
    const float* b1      = (const float*)d_in[5];
    const float* W2      = (const float*)d_in[6];
    const float* b2      = (const float*)d_in[7];
    const float* W3      = (const float*)d_in[8];
    const float* b3      = (const float*)d_in[9];
    float*       out     = (float*)d_out;

    cudaFuncSetAttribute(mlp_mma_kernel,
                         cudaFuncAttributeMaxDynamicSharedMemorySize, SMEM_TOTAL);

    prep_kernel<<<144, 256>>>(W0, W1, W2);   // also resets g_cnt

    dim3 grid(BATCH / 64, ATOMS);
    mlp_mma_kernel<<<grid, 256, SMEM_TOTAL>>>(x, species, b0, b1, b2, W3, b3, out);
}